// round 8
// baseline (speedup 1.0000x reference)
#include <cuda_runtime.h>
#include <math.h>
#include <stdint.h>

#define NN 10000
#define NE 160000
#define H 128
#define NRBF 32
#define NG 128
#define NOUT 65
#define PADX 132
#define ETILE 128
#define NTILES (NE/ETILE)
#define PADT 132   // row stride (floats) for ts / fs / W1t / D

// ---------------- scratch (device globals; no allocation) ----------------
__device__ float g_x[NN*H];
__device__ float g_vec[NN*3*H];
__device__ float g_dx[NN*H];        // reused as vnorm buffer at the end
__device__ float g_dvec[NN*3*H];    // reused as 'a' activations at the end
__device__ float g_vmix[NN*3*H];    // reused as v2 in the final stage
__device__ float g_dirn[NE*3];
__device__ float g_rbf[NE*NRBF];
__device__ float g_pooled[NG*NOUT];

__device__ __forceinline__ float silu_f(float v){ return v / (1.0f + expf(-v)); }

__device__ __forceinline__ void red4(float* p, float a, float b, float c, float d){
  asm volatile("red.global.add.v4.f32 [%0], {%1,%2,%3,%4};"
               :: "l"(p), "f"(a), "f"(b), "f"(c), "f"(d) : "memory");
}

// ---- f32x2 packed FMA helpers ----
__device__ __forceinline__ void ffma2(unsigned long long& d, unsigned long long a, unsigned long long b){
  asm("fma.rn.f32x2 %0, %1, %2, %0;" : "+l"(d) : "l"(a), "l"(b));
}
__device__ __forceinline__ unsigned long long bcast2(float x){
  unsigned long long r; asm("mov.b64 %0, {%1, %1};" : "=l"(r) : "f"(x)); return r;
}
__device__ __forceinline__ void unpack2(unsigned long long v, float& lo, float& hi){
  asm("mov.b64 {%0, %1}, %2;" : "=f"(lo), "=f"(hi) : "l"(v));
}

// ---- tf32 helpers ----
__device__ __forceinline__ unsigned tf32_of(float x){
  unsigned r; asm("cvt.rna.tf32.f32 %0, %1;" : "=r"(r) : "f"(x)); return r;
}
// split x into hi (tf32 bits) and lo (tf32 bits of residual)
__device__ __forceinline__ void tf32_split(float x, unsigned& hi, unsigned& lo){
  hi = tf32_of(x);
  float r = x - __uint_as_float(hi);
  lo = tf32_of(r);
}

// mma.sync m16n8k8 tf32, D(f32) accumulate
__device__ __forceinline__ void mma8(float* d, const unsigned* a, const unsigned* b){
  asm volatile(
    "mma.sync.aligned.m16n8k8.row.col.f32.tf32.tf32.f32 "
    "{%0,%1,%2,%3}, {%4,%5,%6,%7}, {%8,%9}, {%0,%1,%2,%3};"
    : "+f"(d[0]),"+f"(d[1]),"+f"(d[2]),"+f"(d[3])
    : "r"(a[0]),"r"(a[1]),"r"(a[2]),"r"(a[3]), "r"(b[0]),"r"(b[1]));
}

// ---------------- init ----------------
__global__ void k_init(const int* __restrict__ z, const float* __restrict__ emb){
  int idx = blockIdx.x*blockDim.x + threadIdx.x;
  if (idx < NN*3*H){ g_vec[idx] = 0.0f; g_vmix[idx] = 0.0f; }
  if (idx < NN*H){ int n = idx >> 7, h = idx & 127; g_x[idx] = emb[z[n]*H + h]; }
  if (idx < NG*NOUT) g_pooled[idx] = 0.0f;
}

__global__ void k_zero(){
  int idx = blockIdx.x*blockDim.x + threadIdx.x;
  if (idx < NN*3*H) g_dvec[idx] = 0.0f;
  if (idx < NN*H)   g_dx[idx]   = 0.0f;
}

__global__ void k_vecadd(){
  int idx = blockIdx.x*blockDim.x + threadIdx.x;
  if (idx < NN*3*H) g_vec[idx] += g_dvec[idx];
}

// ---------------- edge geometry: dirn + rbf (once) ----------------
__global__ void k_edgegeom(const int* __restrict__ ei, const float* __restrict__ pos){
  int e = blockIdx.x*blockDim.x + threadIdx.x;
  if (e >= NE) return;
  int s = ei[e], d = ei[NE + e];
  float dx = pos[d*3+0]-pos[s*3+0];
  float dy = pos[d*3+1]-pos[s*3+1];
  float dz = pos[d*3+2]-pos[s*3+2];
  float r = sqrtf(dx*dx + dy*dy + dz*dz + 1e-8f);
  float inv = 1.0f/r;
  g_dirn[e*3+0] = dx*inv; g_dirn[e*3+1] = dy*inv; g_dirn[e*3+2] = dz*inv;
  float m0 = expf(-5.0f);
  float dm = (1.0f - m0) / (float)(NRBF - 1);
  float tb = (2.0f/(float)NRBF) * (1.0f - m0);
  float beta = 1.0f/(tb*tb);
  float cut = (r < 5.0f) ? 0.5f*(cosf(3.14159265358979323846f * r * 0.2f) + 1.0f) : 0.0f;
  float al = expf(-r);
  #pragma unroll
  for (int i = 0; i < NRBF; ++i){
    float df = al - (m0 + (float)i * dm);
    g_rbf[e*NRBF + i] = cut * expf(-beta*df*df);
  }
}

// ---------------- node GEMM (FFMA2): Y[rows,128] (+)= X[rows,128] @ W[128,128] ----------------
template<bool ACC>
__global__ __launch_bounds__(128, 2)
void gemm_nk(const float* __restrict__ X, const float* __restrict__ W,
             float* __restrict__ Y, int rows){
  extern __shared__ float sm[];
  float* Ws = sm;            // 128*128
  float* Xs = Ws + H*H;      // 64*PADX
  int tid = threadIdx.x;
  int tcol = tid & 15, trow = tid >> 4;
  for (int i = tid; i < H*H; i += 128) Ws[i] = W[i];
  int ntiles = (rows + 63) >> 6;
  for (int t = blockIdx.x; t < ntiles; t += gridDim.x){
    __syncthreads();
    int r0 = t << 6;
    for (int i = tid; i < 64*H; i += 128){
      int rr = i >> 7, kk = i & 127;
      Xs[rr*PADX + kk] = (r0 + rr < rows) ? X[(size_t)(r0+rr)*H + kk] : 0.0f;
    }
    __syncthreads();
    unsigned long long acc2[8][4];
    #pragma unroll
    for (int r=0;r<8;++r){ acc2[r][0]=0ULL; acc2[r][1]=0ULL; acc2[r][2]=0ULL; acc2[r][3]=0ULL; }
    #pragma unroll 2
    for (int k0 = 0; k0 < H; k0 += 4){
      float4 xv[8];
      #pragma unroll
      for (int r=0;r<8;++r) xv[r] = *(const float4*)&Xs[(trow*8+r)*PADX + k0];
      #pragma unroll
      for (int kk=0;kk<4;++kk){
        ulonglong2 wA = *(const ulonglong2*)&Ws[(k0+kk)*H + tcol*8];
        ulonglong2 wB = *(const ulonglong2*)&Ws[(k0+kk)*H + tcol*8+4];
        #pragma unroll
        for (int r=0;r<8;++r){
          float x = (kk==0)?xv[r].x:(kk==1)?xv[r].y:(kk==2)?xv[r].z:xv[r].w;
          unsigned long long xb = bcast2(x);
          ffma2(acc2[r][0], xb, wA.x); ffma2(acc2[r][1], xb, wA.y);
          ffma2(acc2[r][2], xb, wB.x); ffma2(acc2[r][3], xb, wB.y);
        }
      }
    }
    #pragma unroll
    for (int r=0;r<8;++r){
      int row = r0 + trow*8 + r;
      if (row < rows){
        float o[8];
        unpack2(acc2[r][0], o[0], o[1]); unpack2(acc2[r][1], o[2], o[3]);
        unpack2(acc2[r][2], o[4], o[5]); unpack2(acc2[r][3], o[6], o[7]);
        float4* yp = (float4*)&Y[(size_t)row*H + tcol*8];
        float4 v0 = make_float4(o[0],o[1],o[2],o[3]);
        float4 v1 = make_float4(o[4],o[5],o[6],o[7]);
        if (ACC){
          float4 a0=yp[0], a1=yp[1];
          v0.x+=a0.x; v0.y+=a0.y; v0.z+=a0.z; v0.w+=a0.w;
          v1.x+=a1.x; v1.y+=a1.y; v1.z+=a1.z; v1.w+=a1.w;
        }
        yp[0]=v0; yp[1]=v1;
      }
    }
  }
}

// ---------------- fused edge kernel: mma.sync tf32x3 for phi ----------------
// 512 threads (16 warps). Per 128-edge tile:
//   filt = rbf@W_rbf (FFMA2, regs) ; ts = x[src]*filt (fp32, smem)
//   phi  = silu(ts @ W1) via mma.sync m16n8k8 tf32 (hi/lo split, 3 passes)
//   D frags -> smem (reuse ts) -> per-edge red4 scatter (dx, dvec)
__global__ __launch_bounds__(512, 1)
void k_edge(const int* __restrict__ ei, const float* __restrict__ Wrbf,
            const float* __restrict__ W1, int hasv){
  extern __shared__ float sm[];
  float* Wr   = sm;                  // 32*128
  float* W1t  = Wr + NRBF*H;         // 128*PADT : W1t[n][k] = W1[k][n]
  float* ts   = W1t + H*PADT;        // 128*PADT : A, then reused for D
  float* fs   = ts + H*PADT;         // 128*PADT : filt (fp32) for scatter
  float* dirs = fs + H*PADT;         // 384
  int*   srcs = (int*)(dirs + 384);  // 128
  int*   dsts = srcs + ETILE;        // 128

  int tid = threadIdx.x, lane = tid & 31, wid = tid >> 5;
  int wm = wid & 3, wn = wid >> 2;            // warp tile: rows wm*32, cols wn*32
  int qr = lane >> 2, qc = lane & 3;          // quad row / col within fragment
  int tcol = tid & 15, trow = tid >> 4;       // staging layout: 4 edges x 8 cols

  for (int i = tid; i < NRBF*H; i += 512) Wr[i] = Wrbf[i];
  for (int i = tid; i < H*H; i += 512){
    int k = i >> 7, n = i & 127;             // coalesced read of W1[k][n]
    W1t[n*PADT + k] = W1[i];
  }

  // scatter mapping: thread owns edge e_loc, 32-col window cb
  int e_loc = tid & 127;
  int cb    = (tid >> 7) * 32;

  for (int t = blockIdx.x; t < NTILES; t += gridDim.x){
    __syncthreads();   // previous tile fully consumed
    int e0 = t * ETILE;
    if (tid < ETILE) srcs[tid] = ei[e0 + tid];
    else if (tid < 2*ETILE) dsts[tid - ETILE] = ei[NE + e0 + (tid - ETILE)];
    for (int i = tid; i < ETILE*3; i += 512) dirs[i] = g_dirn[(size_t)e0*3 + i];

    // ---- filt = rbf @ W_rbf (FFMA2, 4 edges x 8 cols per thread) ----
    unsigned long long f2[4][4];
    #pragma unroll
    for (int e=0;e<4;++e){ f2[e][0]=0ULL; f2[e][1]=0ULL; f2[e][2]=0ULL; f2[e][3]=0ULL; }
    #pragma unroll
    for (int k0 = 0; k0 < NRBF; k0 += 4){
      float4 xv[4];
      #pragma unroll
      for (int e=0;e<4;++e)
        xv[e] = *(const float4*)&g_rbf[(size_t)(e0 + trow*4 + e)*NRBF + k0];
      #pragma unroll
      for (int kk=0;kk<4;++kk){
        ulonglong2 wA = *(const ulonglong2*)&Wr[(k0+kk)*H + tcol*8];
        ulonglong2 wB = *(const ulonglong2*)&Wr[(k0+kk)*H + tcol*8+4];
        #pragma unroll
        for (int e=0;e<4;++e){
          float x = (kk==0)?xv[e].x:(kk==1)?xv[e].y:(kk==2)?xv[e].z:xv[e].w;
          unsigned long long xb = bcast2(x);
          ffma2(f2[e][0], xb, wA.x); ffma2(f2[e][1], xb, wA.y);
          ffma2(f2[e][2], xb, wB.x); ffma2(f2[e][3], xb, wB.y);
        }
      }
    }
    float f[4][8];
    #pragma unroll
    for (int e=0;e<4;++e){
      unpack2(f2[e][0], f[e][0], f[e][1]); unpack2(f2[e][1], f[e][2], f[e][3]);
      unpack2(f2[e][2], f[e][4], f[e][5]); unpack2(f2[e][3], f[e][6], f[e][7]);
    }
    __syncthreads();   // srcs/dsts/dirs visible

    // ---- ts = x[src] * filt (fp32) ; fs = filt ----
    #pragma unroll
    for (int e=0;e<4;++e){
      int row = trow*4 + e;
      int s = srcs[row];
      const float* xp = &g_x[(size_t)s*H + tcol*8];
      float4 xa = *(const float4*)xp;
      float4 xb = *(const float4*)(xp+4);
      if (hasv){
        *(float4*)&fs[row*PADT + tcol*8]     = make_float4(f[e][0],f[e][1],f[e][2],f[e][3]);
        *(float4*)&fs[row*PADT + tcol*8 + 4] = make_float4(f[e][4],f[e][5],f[e][6],f[e][7]);
      }
      *(float4*)&ts[row*PADT + tcol*8] =
        make_float4(xa.x*f[e][0], xa.y*f[e][1], xa.z*f[e][2], xa.w*f[e][3]);
      *(float4*)&ts[row*PADT + tcol*8 + 4] =
        make_float4(xb.x*f[e][4], xb.y*f[e][5], xb.z*f[e][6], xb.w*f[e][7]);
    }
    __syncthreads();   // ts complete

    // ---- phi GEMM: tf32x3 mma.sync ----
    float d[2][4][4];
    #pragma unroll
    for (int ms=0;ms<2;++ms)
      #pragma unroll
      for (int ns=0;ns<4;++ns){ d[ms][ns][0]=0.f; d[ms][ns][1]=0.f; d[ms][ns][2]=0.f; d[ms][ns][3]=0.f; }

    #pragma unroll 4
    for (int ks = 0; ks < 16; ++ks){
      int k0 = ks*8 + qc;
      unsigned ahi[2][4], alo[2][4];
      #pragma unroll
      for (int ms=0;ms<2;++ms){
        int r = wm*32 + ms*16 + qr;
        tf32_split(ts[r*PADT + k0],         ahi[ms][0], alo[ms][0]);
        tf32_split(ts[(r+8)*PADT + k0],     ahi[ms][1], alo[ms][1]);
        tf32_split(ts[r*PADT + k0 + 4],     ahi[ms][2], alo[ms][2]);
        tf32_split(ts[(r+8)*PADT + k0 + 4], ahi[ms][3], alo[ms][3]);
      }
      unsigned bhi[4][2], blo[4][2];
      #pragma unroll
      for (int ns=0;ns<4;++ns){
        int n = wn*32 + ns*8 + qr;
        tf32_split(W1t[n*PADT + k0],     bhi[ns][0], blo[ns][0]);
        tf32_split(W1t[n*PADT + k0 + 4], bhi[ns][1], blo[ns][1]);
      }
      #pragma unroll
      for (int ms=0;ms<2;++ms)
        #pragma unroll
        for (int ns=0;ns<4;++ns){
          mma8(d[ms][ns], ahi[ms], bhi[ns]);
          mma8(d[ms][ns], ahi[ms], blo[ns]);
          mma8(d[ms][ns], alo[ms], bhi[ns]);
        }
    }
    __syncthreads();   // all warps done reading ts

    // ---- store D fragments to smem (reuse ts) ----
    #pragma unroll
    for (int ms=0;ms<2;++ms){
      int r = wm*32 + ms*16 + qr;
      #pragma unroll
      for (int ns=0;ns<4;++ns){
        int c = wn*32 + ns*8 + 2*qc;
        *(float2*)&ts[r*PADT + c]     = make_float2(d[ms][ns][0], d[ms][ns][1]);
        *(float2*)&ts[(r+8)*PADT + c] = make_float2(d[ms][ns][2], d[ms][ns][3]);
      }
    }
    __syncthreads();

    // ---- silu + scatter: thread owns edge e_loc, cols [cb, cb+32) ----
    float p[32];
    #pragma unroll
    for (int j=0;j<8;++j){
      float4 v = *(const float4*)&ts[e_loc*PADT + cb + j*4];
      p[4*j]   = silu_f(v.x); p[4*j+1] = silu_f(v.y);
      p[4*j+2] = silu_f(v.z); p[4*j+3] = silu_f(v.w);
    }
    int s = srcs[e_loc], dn = dsts[e_loc];
    float dcs[3] = {dirs[e_loc*3+0], dirs[e_loc*3+1], dirs[e_loc*3+2]};
    #pragma unroll
    for (int j=0;j<8;++j)
      red4(&g_dx[(size_t)dn*H + cb + j*4], p[4*j], p[4*j+1], p[4*j+2], p[4*j+3]);
    if (hasv){
      float4 fv[8];
      #pragma unroll
      for (int j=0;j<8;++j) fv[j] = *(const float4*)&fs[e_loc*PADT + cb + j*4];
      #pragma unroll
      for (int c=0;c<3;++c){
        #pragma unroll
        for (int j=0;j<8;++j){
          float4 vm = *(const float4*)&g_vmix[((size_t)s*3 + c)*H + cb + j*4];
          red4(&g_dvec[((size_t)dn*3 + c)*H + cb + j*4],
               vm.x*fv[j].x + p[4*j]*dcs[c],   vm.y*fv[j].y + p[4*j+1]*dcs[c],
               vm.z*fv[j].z + p[4*j+2]*dcs[c], vm.w*fv[j].w + p[4*j+3]*dcs[c]);
        }
      }
    } else {
      #pragma unroll
      for (int c=0;c<3;++c){
        #pragma unroll
        for (int j=0;j<8;++j)
          red4(&g_dvec[((size_t)dn*3 + c)*H + cb + j*4],
               p[4*j]*dcs[c], p[4*j+1]*dcs[c], p[4*j+2]*dcs[c], p[4*j+3]*dcs[c]);
      }
    }
  }
}

// ---------------- vnorm ----------------
__global__ void k_vnorm(){
  int idx = blockIdx.x*blockDim.x + threadIdx.x;
  if (idx >= NN*H) return;
  int n = idx >> 7, h = idx & 127;
  float a0 = g_vmix[((size_t)n*3+0)*H + h];
  float a1 = g_vmix[((size_t)n*3+1)*H + h];
  float a2 = g_vmix[((size_t)n*3+2)*H + h];
  g_dx[idx] = sqrtf(a0*a0 + a1*a1 + a2*a2 + 1e-8f);
}

// ---------------- a = silu([x, vnorm] @ Wa + ba) (FFMA2) ----------------
#define PADA 264
__global__ __launch_bounds__(256, 1)
void k_mlp_a(const float* __restrict__ Wa, const float* __restrict__ ba){
  extern __shared__ float sm[];
  float* Was = sm;               // 256*128
  float* Xs  = Was + 256*H;      // 64*PADA
  float* bas = Xs + 64*PADA;     // 128
  int tid = threadIdx.x;
  int tcol = tid & 15, trow = tid >> 4;
  for (int i = tid; i < 256*H; i += 256) Was[i] = Wa[i];
  if (tid < H) bas[tid] = ba[tid];
  int ntiles = (NN + 63) >> 6;
  for (int t = blockIdx.x; t < ntiles; t += gridDim.x){
    __syncthreads();
    int r0 = t << 6;
    for (int i = tid; i < 64*256; i += 256){
      int rr = i >> 8, kk = i & 255;
      float v = 0.0f;
      if (r0 + rr < NN)
        v = (kk < H) ? g_x[(size_t)(r0+rr)*H + kk] : g_dx[(size_t)(r0+rr)*H + (kk-H)];
      Xs[rr*PADA + kk] = v;
    }
    __syncthreads();
    unsigned long long acc2[4][4];
    #pragma unroll
    for (int r=0;r<4;++r){ acc2[r][0]=0ULL; acc2[r][1]=0ULL; acc2[r][2]=0ULL; acc2[r][3]=0ULL; }
    #pragma unroll 2
    for (int k0 = 0; k0 < 256; k0 += 4){
      float4 xv[4];
      #pragma unroll
      for (int r=0;r<4;++r) xv[r] = *(const float4*)&Xs[(trow*4+r)*PADA + k0];
      #pragma unroll
      for (int kk=0;kk<4;++kk){
        ulonglong2 wA = *(const ulonglong2*)&Was[(k0+kk)*H + tcol*8];
        ulonglong2 wB = *(const ulonglong2*)&Was[(k0+kk)*H + tcol*8+4];
        #pragma unroll
        for (int r=0;r<4;++r){
          float x = (kk==0)?xv[r].x:(kk==1)?xv[r].y:(kk==2)?xv[r].z:xv[r].w;
          unsigned long long xb = bcast2(x);
          ffma2(acc2[r][0], xb, wA.x); ffma2(acc2[r][1], xb, wA.y);
          ffma2(acc2[r][2], xb, wB.x); ffma2(acc2[r][3], xb, wB.y);
        }
      }
    }
    #pragma unroll
    for (int r=0;r<4;++r){
      int row = r0 + trow*4 + r;
      if (row < NN){
        float o[8];
        unpack2(acc2[r][0], o[0], o[1]); unpack2(acc2[r][1], o[2], o[3]);
        unpack2(acc2[r][2], o[4], o[5]); unpack2(acc2[r][3], o[6], o[7]);
        float* ap = &g_dvec[(size_t)row*H + tcol*8];
        #pragma unroll
        for (int c=0;c<8;++c) ap[c] = silu_f(o[c] + bas[tcol*8+c]);
      }
    }
  }
}

// ---------------- out = a @ Wb + bb, pooled atomics ----------------
__global__ void k_poolout(const int* __restrict__ batch, const float* __restrict__ Wb,
                          const float* __restrict__ bb){
  extern __shared__ float sm[];
  float* Wbs = sm;
  float* bbs = Wbs + H*NOUT;
  float* as_ = bbs + NOUT;
  int tid = threadIdx.x;
  for (int i = tid; i < H*NOUT; i += 128) Wbs[i] = Wb[i];
  if (tid < NOUT) bbs[tid] = bb[tid];
  for (int n = blockIdx.x; n < NN; n += gridDim.x){
    __syncthreads();
    as_[tid] = g_dvec[(size_t)n*H + tid];
    __syncthreads();
    if (tid < NOUT){
      float o = bbs[tid];
      #pragma unroll 4
      for (int h = 0; h < H; ++h) o += as_[h] * Wbs[h*NOUT + tid];
      atomicAdd(&g_pooled[batch[n]*NOUT + tid], o);
    }
  }
}

// ---------------- output assembly ----------------
__global__ void k_out(float* __restrict__ out){
  int idx = blockIdx.x*blockDim.x + threadIdx.x;
  if (idx < NG*64){
    int g = idx >> 6, j = idx & 63;
    out[idx] = g_pooled[g*NOUT + j];
  } else if (idx < NG*64 + NG){
    int g = idx - NG*64;
    float v = g_pooled[g*NOUT + 64];
    out[idx] = fminf(fmaxf(v, -10.0f), 2.0f);
  }
}

// ---------------- launch ----------------
extern "C" void kernel_launch(void* const* d_in, const int* in_sizes, int n_in,
                              void* d_out, int out_size){
  const int*   z     = (const int*)  d_in[0];
  const float* pos   = (const float*)d_in[1];
  const int*   batch = (const int*)  d_in[2];
  const int*   ei    = (const int*)  d_in[3];
  const float* emb   = (const float*)d_in[4];
  const float* Wrbf  = (const float*)d_in[5];
  const float* W1    = (const float*)d_in[6];
  const float* Wo    = (const float*)d_in[7];
  const float* Wv    = (const float*)d_in[8];
  const float* Wvec2 = (const float*)d_in[10];
  const float* Wa    = (const float*)d_in[11];
  const float* ba    = (const float*)d_in[12];
  const float* Wb    = (const float*)d_in[13];
  const float* bb    = (const float*)d_in[14];
  float* out = (float*)d_out;

  float *p_x, *p_vec, *p_dx, *p_dvec, *p_vmix;
  cudaGetSymbolAddress((void**)&p_x,    g_x);
  cudaGetSymbolAddress((void**)&p_vec,  g_vec);
  cudaGetSymbolAddress((void**)&p_dx,   g_dx);
  cudaGetSymbolAddress((void**)&p_dvec, g_dvec);
  cudaGetSymbolAddress((void**)&p_vmix, g_vmix);

  const size_t gemm_smem = (size_t)(H*H + 64*PADX) * sizeof(float);
  const size_t edge_smem = (size_t)(NRBF*H + 3*H*PADT + 384) * sizeof(float)
                         + 2*ETILE*sizeof(int);
  const size_t mlpa_smem = (size_t)(256*H + 64*PADA + H) * sizeof(float);
  const size_t pool_smem = (size_t)(H*NOUT + NOUT + H) * sizeof(float);

  cudaFuncSetAttribute(gemm_nk<false>, cudaFuncAttributeMaxDynamicSharedMemorySize, (int)gemm_smem);
  cudaFuncSetAttribute(gemm_nk<true>,  cudaFuncAttributeMaxDynamicSharedMemorySize, (int)gemm_smem);
  cudaFuncSetAttribute(k_edge,         cudaFuncAttributeMaxDynamicSharedMemorySize, (int)edge_smem);
  cudaFuncSetAttribute(k_mlp_a,        cudaFuncAttributeMaxDynamicSharedMemorySize, (int)mlpa_smem);
  cudaFuncSetAttribute(k_poolout,      cudaFuncAttributeMaxDynamicSharedMemorySize, (int)pool_smem);

  const int ZB = (NN*3*H + 255) / 256;

  k_init<<<ZB, 256>>>(z, emb);
  k_edgegeom<<<(NE + 255)/256, 256>>>(ei, pos);

  for (int l = 0; l < 2; ++l){
    k_zero<<<ZB, 256>>>();
    if (l > 0)  // layer 0: vec == 0, g_vmix pre-zeroed by k_init
      gemm_nk<false><<<296, 128, gemm_smem>>>(p_vec, Wv + (size_t)l*H*H, p_vmix, NN*3);
    k_edge<<<148, 512, edge_smem>>>(ei, Wrbf + (size_t)l*NRBF*H, W1 + (size_t)l*H*H, l);
    gemm_nk<true><<<296, 128, gemm_smem>>>(p_dx, Wo + (size_t)l*H*H, p_x, NN);
    k_vecadd<<<ZB, 256>>>();
  }

  gemm_nk<false><<<296, 128, gemm_smem>>>(p_vec, Wvec2, p_vmix, NN*3);
  k_vnorm<<<(NN*H + 255)/256, 256>>>();
  k_mlp_a<<<157, 256, mlpa_smem>>>(Wa, ba);
  k_poolout<<<592, 128, pool_smem>>>(batch, Wb, bb);
  k_out<<<(NG*64 + NG + 255)/256, 256>>>(out);
}

// round 10
// speedup vs baseline: 1.2703x; 1.2703x over previous
#include <cuda_runtime.h>
#include <math.h>
#include <stdint.h>

#define NN 10000
#define NE 160000
#define H 128
#define NRBF 32
#define NG 128
#define NOUT 65
#define PADX 132
#define ETILE 128
#define NTILES (NE/ETILE)
#define PADT 132   // row stride (floats/uints) for ts / W1hi / W1lo

// ---------------- scratch (device globals; no allocation) ----------------
__device__ float g_x[NN*H];
__device__ float g_vec[NN*3*H];
__device__ float g_dx[NN*H];        // reused as vnorm buffer at the end
__device__ float g_dvec[NN*3*H];    // reused as 'a' activations at the end
__device__ float g_vmix[NN*3*H];    // reused as v2 in the final stage
__device__ float g_dirn[NE*3];
__device__ float g_rbf[NE*NRBF];
__device__ float g_pooled[NG*NOUT];

__device__ __forceinline__ float silu_f(float v){ return v / (1.0f + expf(-v)); }

__device__ __forceinline__ void red4(float* p, float a, float b, float c, float d){
  asm volatile("red.global.add.v4.f32 [%0], {%1,%2,%3,%4};"
               :: "l"(p), "f"(a), "f"(b), "f"(c), "f"(d) : "memory");
}

// ---- tf32 helpers ----
__device__ __forceinline__ unsigned tf32_of(float x){
  unsigned r; asm("cvt.rna.tf32.f32 %0, %1;" : "=r"(r) : "f"(x)); return r;
}
__device__ __forceinline__ void tf32_split(float x, unsigned& hi, unsigned& lo){
  hi = tf32_of(x);
  float r = x - __uint_as_float(hi);
  lo = tf32_of(r);
}

// mma.sync m16n8k8 tf32, D(f32) accumulate
__device__ __forceinline__ void mma8(float* d, const unsigned* a, const unsigned* b){
  asm volatile(
    "mma.sync.aligned.m16n8k8.row.col.f32.tf32.tf32.f32 "
    "{%0,%1,%2,%3}, {%4,%5,%6,%7}, {%8,%9}, {%0,%1,%2,%3};"
    : "+f"(d[0]),"+f"(d[1]),"+f"(d[2]),"+f"(d[3])
    : "r"(a[0]),"r"(a[1]),"r"(a[2]),"r"(a[3]), "r"(b[0]),"r"(b[1]));
}

// ---------------- init ----------------
__global__ void k_init(const int* __restrict__ z, const float* __restrict__ emb){
  int idx = blockIdx.x*blockDim.x + threadIdx.x;
  if (idx < NN*3*H){ g_vec[idx] = 0.0f; g_vmix[idx] = 0.0f; }
  if (idx < NN*H){ int n = idx >> 7, h = idx & 127; g_x[idx] = emb[z[n]*H + h]; }
  if (idx < NG*NOUT) g_pooled[idx] = 0.0f;
}

__global__ void k_zero(){
  int idx = blockIdx.x*blockDim.x + threadIdx.x;
  if (idx < NN*3*H) g_dvec[idx] = 0.0f;
  if (idx < NN*H)   g_dx[idx]   = 0.0f;
}

__global__ void k_vecadd(){
  int idx = blockIdx.x*blockDim.x + threadIdx.x;
  if (idx < NN*3*H) g_vec[idx] += g_dvec[idx];
}

// ---------------- edge geometry: dirn + rbf (once) ----------------
__global__ void k_edgegeom(const int* __restrict__ ei, const float* __restrict__ pos){
  int e = blockIdx.x*blockDim.x + threadIdx.x;
  if (e >= NE) return;
  int s = ei[e], d = ei[NE + e];
  float dx = pos[d*3+0]-pos[s*3+0];
  float dy = pos[d*3+1]-pos[s*3+1];
  float dz = pos[d*3+2]-pos[s*3+2];
  float r = sqrtf(dx*dx + dy*dy + dz*dz + 1e-8f);
  float inv = 1.0f/r;
  g_dirn[e*3+0] = dx*inv; g_dirn[e*3+1] = dy*inv; g_dirn[e*3+2] = dz*inv;
  float m0 = expf(-5.0f);
  float dm = (1.0f - m0) / (float)(NRBF - 1);
  float tb = (2.0f/(float)NRBF) * (1.0f - m0);
  float beta = 1.0f/(tb*tb);
  float cut = (r < 5.0f) ? 0.5f*(cosf(3.14159265358979323846f * r * 0.2f) + 1.0f) : 0.0f;
  float al = expf(-r);
  #pragma unroll
  for (int i = 0; i < NRBF; ++i){
    float df = al - (m0 + (float)i * dm);
    g_rbf[e*NRBF + i] = cut * expf(-beta*df*df);
  }
}

// ---------------- node GEMM (round-4 form): Y[rows,128] (+)= X[rows,128] @ W ----------------
template<bool ACC>
__global__ __launch_bounds__(128, 2)
void gemm_nk(const float* __restrict__ X, const float* __restrict__ W,
             float* __restrict__ Y, int rows){
  extern __shared__ float sm[];
  float* Ws = sm;            // 128*128
  float* Xs = Ws + H*H;      // 64*PADX
  int tid = threadIdx.x;
  int tcol = tid & 15, trow = tid >> 4;
  for (int i = tid; i < H*H; i += 128) Ws[i] = W[i];
  int ntiles = (rows + 63) >> 6;
  for (int t = blockIdx.x; t < ntiles; t += gridDim.x){
    __syncthreads();
    int r0 = t << 6;
    for (int i = tid; i < 64*H; i += 128){
      int rr = i >> 7, kk = i & 127;
      Xs[rr*PADX + kk] = (r0 + rr < rows) ? X[(size_t)(r0+rr)*H + kk] : 0.0f;
    }
    __syncthreads();
    float acc[8][8];
    #pragma unroll
    for (int r=0;r<8;++r){
      #pragma unroll
      for (int c=0;c<8;++c) acc[r][c]=0.f;
    }
    #pragma unroll 2
    for (int k0 = 0; k0 < H; k0 += 4){
      float4 xv[8];
      #pragma unroll
      for (int r=0;r<8;++r) xv[r] = *(const float4*)&Xs[(trow*8+r)*PADX + k0];
      #pragma unroll
      for (int kk=0;kk<4;++kk){
        float4 wa = *(const float4*)&Ws[(k0+kk)*H + tcol*8];
        float4 wb = *(const float4*)&Ws[(k0+kk)*H + tcol*8+4];
        #pragma unroll
        for (int r=0;r<8;++r){
          float x = (kk==0)?xv[r].x:(kk==1)?xv[r].y:(kk==2)?xv[r].z:xv[r].w;
          acc[r][0]+=x*wa.x; acc[r][1]+=x*wa.y; acc[r][2]+=x*wa.z; acc[r][3]+=x*wa.w;
          acc[r][4]+=x*wb.x; acc[r][5]+=x*wb.y; acc[r][6]+=x*wb.z; acc[r][7]+=x*wb.w;
        }
      }
    }
    #pragma unroll
    for (int r=0;r<8;++r){
      int row = r0 + trow*8 + r;
      if (row < rows){
        float4* yp = (float4*)&Y[(size_t)row*H + tcol*8];
        float4 v0 = make_float4(acc[r][0],acc[r][1],acc[r][2],acc[r][3]);
        float4 v1 = make_float4(acc[r][4],acc[r][5],acc[r][6],acc[r][7]);
        if (ACC){
          float4 a0=yp[0], a1=yp[1];
          v0.x+=a0.x; v0.y+=a0.y; v0.z+=a0.z; v0.w+=a0.w;
          v1.x+=a1.x; v1.y+=a1.y; v1.z+=a1.z; v1.w+=a1.w;
        }
        yp[0]=v0; yp[1]=v1;
      }
    }
  }
}

// ---------------- fused edge kernel: mma.sync tf32x3, B hi/lo precomputed ----------------
// 512 threads (16 warps). Per 128-edge tile:
//   filt = rbf@W_rbf (FFMA, regs, thread owns 4 edges x 8 cols)
//   ts   = x[src]*filt (fp32, smem)
//   phi  = silu(ts @ W1) via mma.sync m16n8k8 tf32 (A split in-loop; B hi/lo from smem)
//   D -> smem (reuse ts) -> scatter with SAME 4x8 mapping (filt stays in regs)
__global__ __launch_bounds__(512, 1)
void k_edge(const int* __restrict__ ei, const float* __restrict__ Wrbf,
            const float* __restrict__ W1, int hasv){
  extern __shared__ float sm[];
  float*    Wr   = sm;                         // 32*128
  unsigned* W1hi = (unsigned*)(Wr + NRBF*H);   // [128][PADT] : hi(W1[k][n]) at [n][k]
  unsigned* W1lo = W1hi + H*PADT;              // [128][PADT]
  float*    ts   = (float*)(W1lo + H*PADT);    // [128][PADT] : A, then reused for D
  float*    dirs = ts + H*PADT;                // 384
  int*      srcs = (int*)(dirs + 384);         // 128
  int*      dsts = srcs + ETILE;               // 128

  int tid = threadIdx.x, lane = tid & 31, wid = tid >> 5;
  int wm = wid & 3, wn = wid >> 2;            // warp MMA tile: rows wm*32, cols wn*32
  int qr = lane >> 2, qc = lane & 3;          // quad row / col within fragment
  int tcol = tid & 15, trow = tid >> 4;       // ownership: 4 edges (trow*4..) x 8 cols (tcol*8..)

  for (int i = tid; i < NRBF*H; i += 512) Wr[i] = Wrbf[i];
  for (int i = tid; i < H*H; i += 512){
    int k = i >> 7, n = i & 127;              // coalesced read of W1[k][n]
    unsigned hi, lo;
    tf32_split(W1[i], hi, lo);
    W1hi[n*PADT + k] = hi;
    W1lo[n*PADT + k] = lo;
  }

  for (int t = blockIdx.x; t < NTILES; t += gridDim.x){
    __syncthreads();   // previous tile fully consumed
    int e0 = t * ETILE;
    if (tid < ETILE) srcs[tid] = ei[e0 + tid];
    else if (tid < 2*ETILE) dsts[tid - ETILE] = ei[NE + e0 + (tid - ETILE)];
    for (int i = tid; i < ETILE*3; i += 512) dirs[i] = g_dirn[(size_t)e0*3 + i];

    // ---- filt = rbf @ W_rbf (4 edges x 8 cols per thread) ----
    float f[4][8];
    #pragma unroll
    for (int e=0;e<4;++e){
      #pragma unroll
      for (int c=0;c<8;++c) f[e][c]=0.f;
    }
    #pragma unroll
    for (int k0 = 0; k0 < NRBF; k0 += 4){
      float4 xv[4];
      #pragma unroll
      for (int e=0;e<4;++e)
        xv[e] = *(const float4*)&g_rbf[(size_t)(e0 + trow*4 + e)*NRBF + k0];
      #pragma unroll
      for (int kk=0;kk<4;++kk){
        float4 wa = *(const float4*)&Wr[(k0+kk)*H + tcol*8];
        float4 wb = *(const float4*)&Wr[(k0+kk)*H + tcol*8+4];
        #pragma unroll
        for (int e=0;e<4;++e){
          float x = (kk==0)?xv[e].x:(kk==1)?xv[e].y:(kk==2)?xv[e].z:xv[e].w;
          f[e][0]+=x*wa.x; f[e][1]+=x*wa.y; f[e][2]+=x*wa.z; f[e][3]+=x*wa.w;
          f[e][4]+=x*wb.x; f[e][5]+=x*wb.y; f[e][6]+=x*wb.z; f[e][7]+=x*wb.w;
        }
      }
    }
    __syncthreads();   // srcs/dsts/dirs visible

    // ---- ts = x[src] * filt (fp32) ----
    #pragma unroll
    for (int e=0;e<4;++e){
      int row = trow*4 + e;
      int s = srcs[row];
      const float* xp = &g_x[(size_t)s*H + tcol*8];
      float4 xa = *(const float4*)xp;
      float4 xb = *(const float4*)(xp+4);
      *(float4*)&ts[row*PADT + tcol*8] =
        make_float4(xa.x*f[e][0], xa.y*f[e][1], xa.z*f[e][2], xa.w*f[e][3]);
      *(float4*)&ts[row*PADT + tcol*8 + 4] =
        make_float4(xb.x*f[e][4], xb.y*f[e][5], xb.z*f[e][6], xb.w*f[e][7]);
    }
    __syncthreads();   // ts complete

    // ---- phi GEMM: tf32x3 mma.sync (A split in-loop, B from W1hi/W1lo) ----
    float d[2][4][4];
    #pragma unroll
    for (int ms=0;ms<2;++ms)
      #pragma unroll
      for (int ns=0;ns<4;++ns){ d[ms][ns][0]=0.f; d[ms][ns][1]=0.f; d[ms][ns][2]=0.f; d[ms][ns][3]=0.f; }

    #pragma unroll 4
    for (int ks = 0; ks < 16; ++ks){
      int k0 = ks*8 + qc;
      unsigned ahi[2][4], alo[2][4];
      #pragma unroll
      for (int ms=0;ms<2;++ms){
        int r = wm*32 + ms*16 + qr;
        tf32_split(ts[r*PADT + k0],         ahi[ms][0], alo[ms][0]);
        tf32_split(ts[(r+8)*PADT + k0],     ahi[ms][1], alo[ms][1]);
        tf32_split(ts[r*PADT + k0 + 4],     ahi[ms][2], alo[ms][2]);
        tf32_split(ts[(r+8)*PADT + k0 + 4], ahi[ms][3], alo[ms][3]);
      }
      unsigned bhi[4][2], blo[4][2];
      #pragma unroll
      for (int ns=0;ns<4;++ns){
        int n = wn*32 + ns*8 + qr;
        bhi[ns][0] = W1hi[n*PADT + k0];
        bhi[ns][1] = W1hi[n*PADT + k0 + 4];
        blo[ns][0] = W1lo[n*PADT + k0];
        blo[ns][1] = W1lo[n*PADT + k0 + 4];
      }
      #pragma unroll
      for (int ms=0;ms<2;++ms)
        #pragma unroll
        for (int ns=0;ns<4;++ns){
          mma8(d[ms][ns], ahi[ms], bhi[ns]);
          mma8(d[ms][ns], ahi[ms], blo[ns]);
          mma8(d[ms][ns], alo[ms], bhi[ns]);
        }
    }
    __syncthreads();   // all warps done reading ts

    // ---- store D fragments to smem (reuse ts) ----
    #pragma unroll
    for (int ms=0;ms<2;++ms){
      int r = wm*32 + ms*16 + qr;
      #pragma unroll
      for (int ns=0;ns<4;++ns){
        int c = wn*32 + ns*8 + 2*qc;
        *(float2*)&ts[r*PADT + c]     = make_float2(d[ms][ns][0], d[ms][ns][1]);
        *(float2*)&ts[(r+8)*PADT + c] = make_float2(d[ms][ns][2], d[ms][ns][3]);
      }
    }
    __syncthreads();

    // ---- silu + scatter: thread owns edges trow*4..+3, cols tcol*8..+7 (filt in regs) ----
    #pragma unroll
    for (int e=0;e<4;++e){
      int row = trow*4 + e;
      float4 va = *(const float4*)&ts[row*PADT + tcol*8];
      float4 vb = *(const float4*)&ts[row*PADT + tcol*8 + 4];
      float p[8];
      p[0]=silu_f(va.x); p[1]=silu_f(va.y); p[2]=silu_f(va.z); p[3]=silu_f(va.w);
      p[4]=silu_f(vb.x); p[5]=silu_f(vb.y); p[6]=silu_f(vb.z); p[7]=silu_f(vb.w);
      int s = srcs[row], dn = dsts[row];
      float dcs[3] = {dirs[row*3+0], dirs[row*3+1], dirs[row*3+2]};
      red4(&g_dx[(size_t)dn*H + tcol*8],     p[0], p[1], p[2], p[3]);
      red4(&g_dx[(size_t)dn*H + tcol*8 + 4], p[4], p[5], p[6], p[7]);
      if (hasv){
        #pragma unroll
        for (int c=0;c<3;++c){
          const float* vmp = &g_vmix[((size_t)s*3 + c)*H + tcol*8];
          float4 ma = *(const float4*)vmp;
          float4 mb = *(const float4*)(vmp+4);
          float* dvp = &g_dvec[((size_t)dn*3 + c)*H + tcol*8];
          red4(dvp,   ma.x*f[e][0] + p[0]*dcs[c], ma.y*f[e][1] + p[1]*dcs[c],
                      ma.z*f[e][2] + p[2]*dcs[c], ma.w*f[e][3] + p[3]*dcs[c]);
          red4(dvp+4, mb.x*f[e][4] + p[4]*dcs[c], mb.y*f[e][5] + p[5]*dcs[c],
                      mb.z*f[e][6] + p[6]*dcs[c], mb.w*f[e][7] + p[7]*dcs[c]);
        }
      } else {
        #pragma unroll
        for (int c=0;c<3;++c){
          float* dvp = &g_dvec[((size_t)dn*3 + c)*H + tcol*8];
          red4(dvp,   p[0]*dcs[c], p[1]*dcs[c], p[2]*dcs[c], p[3]*dcs[c]);
          red4(dvp+4, p[4]*dcs[c], p[5]*dcs[c], p[6]*dcs[c], p[7]*dcs[c]);
        }
      }
    }
  }
}

// ---------------- vnorm ----------------
__global__ void k_vnorm(){
  int idx = blockIdx.x*blockDim.x + threadIdx.x;
  if (idx >= NN*H) return;
  int n = idx >> 7, h = idx & 127;
  float a0 = g_vmix[((size_t)n*3+0)*H + h];
  float a1 = g_vmix[((size_t)n*3+1)*H + h];
  float a2 = g_vmix[((size_t)n*3+2)*H + h];
  g_dx[idx] = sqrtf(a0*a0 + a1*a1 + a2*a2 + 1e-8f);
}

// ---------------- a = silu([x, vnorm] @ Wa + ba) (round-4 form) ----------------
#define PADA 264
__global__ __launch_bounds__(256, 1)
void k_mlp_a(const float* __restrict__ Wa, const float* __restrict__ ba){
  extern __shared__ float sm[];
  float* Was = sm;               // 256*128
  float* Xs  = Was + 256*H;      // 64*PADA
  float* bas = Xs + 64*PADA;     // 128
  int tid = threadIdx.x;
  int tcol = tid & 15, trow = tid >> 4;
  for (int i = tid; i < 256*H; i += 256) Was[i] = Wa[i];
  if (tid < H) bas[tid] = ba[tid];
  int ntiles = (NN + 63) >> 6;
  for (int t = blockIdx.x; t < ntiles; t += gridDim.x){
    __syncthreads();
    int r0 = t << 6;
    for (int i = tid; i < 64*256; i += 256){
      int rr = i >> 8, kk = i & 255;
      float v = 0.0f;
      if (r0 + rr < NN)
        v = (kk < H) ? g_x[(size_t)(r0+rr)*H + kk] : g_dx[(size_t)(r0+rr)*H + (kk-H)];
      Xs[rr*PADA + kk] = v;
    }
    __syncthreads();
    float acc[4][8];
    #pragma unroll
    for (int r=0;r<4;++r){
      #pragma unroll
      for (int c=0;c<8;++c) acc[r][c]=0.f;
    }
    #pragma unroll 2
    for (int k0 = 0; k0 < 256; k0 += 4){
      float4 xv[4];
      #pragma unroll
      for (int r=0;r<4;++r) xv[r] = *(const float4*)&Xs[(trow*4+r)*PADA + k0];
      #pragma unroll
      for (int kk=0;kk<4;++kk){
        float4 wa = *(const float4*)&Was[(k0+kk)*H + tcol*8];
        float4 wb = *(const float4*)&Was[(k0+kk)*H + tcol*8+4];
        #pragma unroll
        for (int r=0;r<4;++r){
          float x = (kk==0)?xv[r].x:(kk==1)?xv[r].y:(kk==2)?xv[r].z:xv[r].w;
          acc[r][0]+=x*wa.x; acc[r][1]+=x*wa.y; acc[r][2]+=x*wa.z; acc[r][3]+=x*wa.w;
          acc[r][4]+=x*wb.x; acc[r][5]+=x*wb.y; acc[r][6]+=x*wb.z; acc[r][7]+=x*wb.w;
        }
      }
    }
    #pragma unroll
    for (int r=0;r<4;++r){
      int row = r0 + trow*4 + r;
      if (row < NN){
        float* ap = &g_dvec[(size_t)row*H + tcol*8];
        #pragma unroll
        for (int c=0;c<8;++c) ap[c] = silu_f(acc[r][c] + bas[tcol*8+c]);
      }
    }
  }
}

// ---------------- out = a @ Wb + bb, pooled atomics ----------------
__global__ void k_poolout(const int* __restrict__ batch, const float* __restrict__ Wb,
                          const float* __restrict__ bb){
  extern __shared__ float sm[];
  float* Wbs = sm;
  float* bbs = Wbs + H*NOUT;
  float* as_ = bbs + NOUT;
  int tid = threadIdx.x;
  for (int i = tid; i < H*NOUT; i += 128) Wbs[i] = Wb[i];
  if (tid < NOUT) bbs[tid] = bb[tid];
  for (int n = blockIdx.x; n < NN; n += gridDim.x){
    __syncthreads();
    as_[tid] = g_dvec[(size_t)n*H + tid];
    __syncthreads();
    if (tid < NOUT){
      float o = bbs[tid];
      #pragma unroll 4
      for (int h = 0; h < H; ++h) o += as_[h] * Wbs[h*NOUT + tid];
      atomicAdd(&g_pooled[batch[n]*NOUT + tid], o);
    }
  }
}

// ---------------- output assembly ----------------
__global__ void k_out(float* __restrict__ out){
  int idx = blockIdx.x*blockDim.x + threadIdx.x;
  if (idx < NG*64){
    int g = idx >> 6, j = idx & 63;
    out[idx] = g_pooled[g*NOUT + j];
  } else if (idx < NG*64 + NG){
    int g = idx - NG*64;
    float v = g_pooled[g*NOUT + 64];
    out[idx] = fminf(fmaxf(v, -10.0f), 2.0f);
  }
}

// ---------------- launch ----------------
extern "C" void kernel_launch(void* const* d_in, const int* in_sizes, int n_in,
                              void* d_out, int out_size){
  const int*   z     = (const int*)  d_in[0];
  const float* pos   = (const float*)d_in[1];
  const int*   batch = (const int*)  d_in[2];
  const int*   ei    = (const int*)  d_in[3];
  const float* emb   = (const float*)d_in[4];
  const float* Wrbf  = (const float*)d_in[5];
  const float* W1    = (const float*)d_in[6];
  const float* Wo    = (const float*)d_in[7];
  const float* Wv    = (const float*)d_in[8];
  const float* Wvec2 = (const float*)d_in[10];
  const float* Wa    = (const float*)d_in[11];
  const float* ba    = (const float*)d_in[12];
  const float* Wb    = (const float*)d_in[13];
  const float* bb    = (const float*)d_in[14];
  float* out = (float*)d_out;

  float *p_x, *p_vec, *p_dx, *p_dvec, *p_vmix;
  cudaGetSymbolAddress((void**)&p_x,    g_x);
  cudaGetSymbolAddress((void**)&p_vec,  g_vec);
  cudaGetSymbolAddress((void**)&p_dx,   g_dx);
  cudaGetSymbolAddress((void**)&p_dvec, g_dvec);
  cudaGetSymbolAddress((void**)&p_vmix, g_vmix);

  const size_t gemm_smem = (size_t)(H*H + 64*PADX) * sizeof(float);
  const size_t edge_smem = (size_t)(NRBF*H + 3*H*PADT + 384) * sizeof(float)
                         + 2*ETILE*sizeof(int);
  const size_t mlpa_smem = (size_t)(256*H + 64*PADA + H) * sizeof(float);
  const size_t pool_smem = (size_t)(H*NOUT + NOUT + H) * sizeof(float);

  cudaFuncSetAttribute(gemm_nk<false>, cudaFuncAttributeMaxDynamicSharedMemorySize, (int)gemm_smem);
  cudaFuncSetAttribute(gemm_nk<true>,  cudaFuncAttributeMaxDynamicSharedMemorySize, (int)gemm_smem);
  cudaFuncSetAttribute(k_edge,         cudaFuncAttributeMaxDynamicSharedMemorySize, (int)edge_smem);
  cudaFuncSetAttribute(k_mlp_a,        cudaFuncAttributeMaxDynamicSharedMemorySize, (int)mlpa_smem);
  cudaFuncSetAttribute(k_poolout,      cudaFuncAttributeMaxDynamicSharedMemorySize, (int)pool_smem);

  const int ZB = (NN*3*H + 255) / 256;

  k_init<<<ZB, 256>>>(z, emb);
  k_edgegeom<<<(NE + 255)/256, 256>>>(ei, pos);

  for (int l = 0; l < 2; ++l){
    k_zero<<<ZB, 256>>>();
    if (l > 0)  // layer 0: vec == 0, g_vmix pre-zeroed by k_init
      gemm_nk<false><<<296, 128, gemm_smem>>>(p_vec, Wv + (size_t)l*H*H, p_vmix, NN*3);
    k_edge<<<148, 512, edge_smem>>>(ei, Wrbf + (size_t)l*NRBF*H, W1 + (size_t)l*H*H, l);
    gemm_nk<true><<<296, 128, gemm_smem>>>(p_dx, Wo + (size_t)l*H*H, p_x, NN);
    k_vecadd<<<ZB, 256>>>();
  }

  gemm_nk<false><<<296, 128, gemm_smem>>>(p_vec, Wvec2, p_vmix, NN*3);
  k_vnorm<<<(NN*H + 255)/256, 256>>>();
  k_mlp_a<<<157, 256, mlpa_smem>>>(Wa, ba);
  k_poolout<<<592, 128, pool_smem>>>(batch, Wb, bb);
  k_out<<<(NG*64 + NG + 255)/256, 256>>>(out);
}

// round 12
// speedup vs baseline: 1.3503x; 1.0630x over previous
#include <cuda_runtime.h>
#include <cuda_bf16.h>
#include <math.h>
#include <stdint.h>

#define NN 10000
#define NE 160000
#define H 128
#define NRBF 32
#define NG 128
#define NOUT 65
#define PADX 132
#define ETILE 128
#define NTILES (NE/ETILE)
#define PADT 132   // row stride (floats) for D
#define PADP 68    // row stride (uints) for packed bf16x2 arrays [128][64]

// ---------------- scratch (device globals; no allocation) ----------------
__device__ float g_x[NN*H];
__device__ float g_vec[NN*3*H];
__device__ float g_dx[NN*H];        // reused as vnorm buffer at the end
__device__ float g_dvec[NN*3*H];    // reused as 'a' activations at the end
__device__ float g_vmix[NN*3*H];    // reused as v2 in the final stage
__device__ float g_dirn[NE*3];
__device__ float g_rbf[NE*NRBF];
__device__ float g_pooled[NG*NOUT];

__device__ __forceinline__ float silu_f(float v){ return v / (1.0f + expf(-v)); }

__device__ __forceinline__ void red4(float* p, float a, float b, float c, float d){
  asm volatile("red.global.add.v4.f32 [%0], {%1,%2,%3,%4};"
               :: "l"(p), "f"(a), "f"(b), "f"(c), "f"(d) : "memory");
}

// ---- bf16 split helpers ----
__device__ __forceinline__ void bf16_split(float x, float& hif, float& lof){
  __nv_bfloat16 h = __float2bfloat16_rn(x);
  hif = __bfloat162float(h);
  lof = x - hif;
}
// pack (even k -> low half, odd k -> high half)
__device__ __forceinline__ unsigned pack_bf16(float lo_elem, float hi_elem){
  __nv_bfloat162 h2 = __floats2bfloat162_rn(lo_elem, hi_elem); // .x = low half
  return *(unsigned*)&h2;
}

// mma.sync m16n8k16 bf16, D(f32) accumulate
__device__ __forceinline__ void mma16(float* d, const unsigned* a, const unsigned* b){
  asm volatile(
    "mma.sync.aligned.m16n8k16.row.col.f32.bf16.bf16.f32 "
    "{%0,%1,%2,%3}, {%4,%5,%6,%7}, {%8,%9}, {%0,%1,%2,%3};"
    : "+f"(d[0]),"+f"(d[1]),"+f"(d[2]),"+f"(d[3])
    : "r"(a[0]),"r"(a[1]),"r"(a[2]),"r"(a[3]), "r"(b[0]),"r"(b[1]));
}

// ---------------- init: x = embed[z]; vec/dvec/dx/pooled = 0 ----------------
__global__ void k_init(const int* __restrict__ z, const float* __restrict__ emb){
  int idx = blockIdx.x*blockDim.x + threadIdx.x;
  if (idx < NN*3*H){ g_vec[idx] = 0.0f; g_dvec[idx] = 0.0f; }
  if (idx < NN*H){ int n = idx >> 7, h = idx & 127; g_x[idx] = emb[z[n]*H + h]; g_dx[idx] = 0.0f; }
  if (idx < NG*NOUT) g_pooled[idx] = 0.0f;
}

__global__ void k_zero(){
  int idx = blockIdx.x*blockDim.x + threadIdx.x;
  if (idx < NN*3*H) g_dvec[idx] = 0.0f;
  if (idx < NN*H)   g_dx[idx]   = 0.0f;
}

// ---------------- edge geometry: dirn + rbf (once) ----------------
__global__ void k_edgegeom(const int* __restrict__ ei, const float* __restrict__ pos){
  int e = blockIdx.x*blockDim.x + threadIdx.x;
  if (e >= NE) return;
  int s = ei[e], d = ei[NE + e];
  float dx = pos[d*3+0]-pos[s*3+0];
  float dy = pos[d*3+1]-pos[s*3+1];
  float dz = pos[d*3+2]-pos[s*3+2];
  float r = sqrtf(dx*dx + dy*dy + dz*dz + 1e-8f);
  float inv = 1.0f/r;
  g_dirn[e*3+0] = dx*inv; g_dirn[e*3+1] = dy*inv; g_dirn[e*3+2] = dz*inv;
  float m0 = expf(-5.0f);
  float dm = (1.0f - m0) / (float)(NRBF - 1);
  float tb = (2.0f/(float)NRBF) * (1.0f - m0);
  float beta = 1.0f/(tb*tb);
  float cut = (r < 5.0f) ? 0.5f*(cosf(3.14159265358979323846f * r * 0.2f) + 1.0f) : 0.0f;
  float al = expf(-r);
  #pragma unroll
  for (int i = 0; i < NRBF; ++i){
    float df = al - (m0 + (float)i * dm);
    g_rbf[e*NRBF + i] = cut * expf(-beta*df*df);
  }
}

// ---------------- node GEMM: Y[rows,128] (+)= X[rows,128] @ W ----------------
template<bool ACC>
__global__ __launch_bounds__(128, 2)
void gemm_nk(const float* __restrict__ X, const float* __restrict__ W,
             float* __restrict__ Y, int rows){
  extern __shared__ float sm[];
  float* Ws = sm;            // 128*128
  float* Xs = Ws + H*H;      // 64*PADX
  int tid = threadIdx.x;
  int tcol = tid & 15, trow = tid >> 4;
  for (int i = tid; i < H*H; i += 128) Ws[i] = W[i];
  int ntiles = (rows + 63) >> 6;
  for (int t = blockIdx.x; t < ntiles; t += gridDim.x){
    __syncthreads();
    int r0 = t << 6;
    for (int i = tid; i < 64*H; i += 128){
      int rr = i >> 7, kk = i & 127;
      Xs[rr*PADX + kk] = (r0 + rr < rows) ? X[(size_t)(r0+rr)*H + kk] : 0.0f;
    }
    __syncthreads();
    float acc[8][8];
    #pragma unroll
    for (int r=0;r<8;++r){
      #pragma unroll
      for (int c=0;c<8;++c) acc[r][c]=0.f;
    }
    #pragma unroll 2
    for (int k0 = 0; k0 < H; k0 += 4){
      float4 xv[8];
      #pragma unroll
      for (int r=0;r<8;++r) xv[r] = *(const float4*)&Xs[(trow*8+r)*PADX + k0];
      #pragma unroll
      for (int kk=0;kk<4;++kk){
        float4 wa = *(const float4*)&Ws[(k0+kk)*H + tcol*8];
        float4 wb = *(const float4*)&Ws[(k0+kk)*H + tcol*8+4];
        #pragma unroll
        for (int r=0;r<8;++r){
          float x = (kk==0)?xv[r].x:(kk==1)?xv[r].y:(kk==2)?xv[r].z:xv[r].w;
          acc[r][0]+=x*wa.x; acc[r][1]+=x*wa.y; acc[r][2]+=x*wa.z; acc[r][3]+=x*wa.w;
          acc[r][4]+=x*wb.x; acc[r][5]+=x*wb.y; acc[r][6]+=x*wb.z; acc[r][7]+=x*wb.w;
        }
      }
    }
    #pragma unroll
    for (int r=0;r<8;++r){
      int row = r0 + trow*8 + r;
      if (row < rows){
        float4* yp = (float4*)&Y[(size_t)row*H + tcol*8];
        float4 v0 = make_float4(acc[r][0],acc[r][1],acc[r][2],acc[r][3]);
        float4 v1 = make_float4(acc[r][4],acc[r][5],acc[r][6],acc[r][7]);
        if (ACC){
          float4 a0=yp[0], a1=yp[1];
          v0.x+=a0.x; v0.y+=a0.y; v0.z+=a0.z; v0.w+=a0.w;
          v1.x+=a1.x; v1.y+=a1.y; v1.z+=a1.z; v1.w+=a1.w;
        }
        yp[0]=v0; yp[1]=v1;
      }
    }
  }
}

// ---------------- fused add+GEMM: S = Xa + Xb ; Xa := S ; Y = S @ W ----------------
__global__ __launch_bounds__(128, 2)
void gemm_add(float* __restrict__ Xa, const float* __restrict__ Xb,
              const float* __restrict__ W, float* __restrict__ Y, int rows){
  extern __shared__ float sm[];
  float* Ws = sm;
  float* Xs = Ws + H*H;
  int tid = threadIdx.x;
  int tcol = tid & 15, trow = tid >> 4;
  for (int i = tid; i < H*H; i += 128) Ws[i] = W[i];
  int ntiles = (rows + 63) >> 6;
  for (int t = blockIdx.x; t < ntiles; t += gridDim.x){
    __syncthreads();
    int r0 = t << 6;
    for (int i = tid; i < 64*H; i += 128){
      int rr = i >> 7, kk = i & 127;
      float v = 0.0f;
      if (r0 + rr < rows){
        size_t gi = (size_t)(r0+rr)*H + kk;
        v = Xa[gi] + Xb[gi];
        Xa[gi] = v;
      }
      Xs[rr*PADX + kk] = v;
    }
    __syncthreads();
    float acc[8][8];
    #pragma unroll
    for (int r=0;r<8;++r){
      #pragma unroll
      for (int c=0;c<8;++c) acc[r][c]=0.f;
    }
    #pragma unroll 2
    for (int k0 = 0; k0 < H; k0 += 4){
      float4 xv[8];
      #pragma unroll
      for (int r=0;r<8;++r) xv[r] = *(const float4*)&Xs[(trow*8+r)*PADX + k0];
      #pragma unroll
      for (int kk=0;kk<4;++kk){
        float4 wa = *(const float4*)&Ws[(k0+kk)*H + tcol*8];
        float4 wb = *(const float4*)&Ws[(k0+kk)*H + tcol*8+4];
        #pragma unroll
        for (int r=0;r<8;++r){
          float x = (kk==0)?xv[r].x:(kk==1)?xv[r].y:(kk==2)?xv[r].z:xv[r].w;
          acc[r][0]+=x*wa.x; acc[r][1]+=x*wa.y; acc[r][2]+=x*wa.z; acc[r][3]+=x*wa.w;
          acc[r][4]+=x*wb.x; acc[r][5]+=x*wb.y; acc[r][6]+=x*wb.z; acc[r][7]+=x*wb.w;
        }
      }
    }
    #pragma unroll
    for (int r=0;r<8;++r){
      int row = r0 + trow*8 + r;
      if (row < rows){
        float4* yp = (float4*)&Y[(size_t)row*H + tcol*8];
        yp[0] = make_float4(acc[r][0],acc[r][1],acc[r][2],acc[r][3]);
        yp[1] = make_float4(acc[r][4],acc[r][5],acc[r][6],acc[r][7]);
      }
    }
  }
}

// ---------------- fused edge kernel: bf16x3 mma.m16n8k16, all splits precomputed ----------------
// 512 threads (16 warps). Per 128-edge tile:
//   filt = rbf@W_rbf (FFMA, regs, thread owns 4 edges x 8 cols)
//   ts   = x[src]*filt -> split bf16 hi/lo, packed pairs -> smem (once per element)
//   phi  = silu(ts @ W1) via mma m16n8k16 bf16 x3 (pure LDS + HMMA inner loop)
//   D -> smem (overlays ts region) -> scatter with same 4x8 mapping (filt stays in regs)
__global__ __launch_bounds__(512, 1)
void k_edge(const int* __restrict__ ei, const float* __restrict__ Wrbf,
            const float* __restrict__ W1, int hasv){
  extern __shared__ float sm[];
  float*    Wr    = sm;                            // 32*128 floats
  unsigned* W1hiP = (unsigned*)(Wr + NRBF*H);      // [128][PADP]
  unsigned* W1loP = W1hiP + H*PADP;                // [128][PADP]
  unsigned* tshiP = W1loP + H*PADP;                // [128][PADP]
  unsigned* tsloP = tshiP + H*PADP;                // [128][PADP]
  float*    Dm    = (float*)tshiP;                 // [128][PADT] overlays tshiP+tsloP
  float*    dirs  = (float*)(tsloP + H*PADP);      // 384
  int*      srcs  = (int*)(dirs + 384);            // 128
  int*      dsts  = srcs + ETILE;                  // 128

  int tid = threadIdx.x, lane = tid & 31, wid = tid >> 5;
  int wm = wid & 3, wn = wid >> 2;            // warp MMA tile: rows wm*32, cols wn*32
  int qr = lane >> 2, qc = lane & 3;          // quad row / col
  int tcol = tid & 15, trow = tid >> 4;       // ownership: 4 edges x 8 cols

  for (int i = tid; i < NRBF*H; i += 512) Wr[i] = Wrbf[i];
  // W1 packed hi/lo: entry [n][kp] = {bf16(W1[2kp][n]), bf16(W1[2kp+1][n])}
  for (int i = tid; i < H*(H/2); i += 512){
    int n = i >> 6, kp = i & 63;
    float w0 = W1[(2*kp)*H + n];
    float w1 = W1[(2*kp+1)*H + n];
    float h0,l0,h1,l1;
    bf16_split(w0, h0, l0);
    bf16_split(w1, h1, l1);
    W1hiP[n*PADP + kp] = pack_bf16(h0, h1);
    W1loP[n*PADP + kp] = pack_bf16(l0, l1);
  }

  for (int t = blockIdx.x; t < NTILES; t += gridDim.x){
    __syncthreads();   // previous tile fully consumed
    int e0 = t * ETILE;
    if (tid < ETILE) srcs[tid] = ei[e0 + tid];
    else if (tid < 2*ETILE) dsts[tid - ETILE] = ei[NE + e0 + (tid - ETILE)];
    for (int i = tid; i < ETILE*3; i += 512) dirs[i] = g_dirn[(size_t)e0*3 + i];

    // ---- filt = rbf @ W_rbf (4 edges x 8 cols per thread) ----
    float f[4][8];
    #pragma unroll
    for (int e=0;e<4;++e){
      #pragma unroll
      for (int c=0;c<8;++c) f[e][c]=0.f;
    }
    #pragma unroll
    for (int k0 = 0; k0 < NRBF; k0 += 4){
      float4 xv[4];
      #pragma unroll
      for (int e=0;e<4;++e)
        xv[e] = *(const float4*)&g_rbf[(size_t)(e0 + trow*4 + e)*NRBF + k0];
      #pragma unroll
      for (int kk=0;kk<4;++kk){
        float4 wa = *(const float4*)&Wr[(k0+kk)*H + tcol*8];
        float4 wb = *(const float4*)&Wr[(k0+kk)*H + tcol*8+4];
        #pragma unroll
        for (int e=0;e<4;++e){
          float x = (kk==0)?xv[e].x:(kk==1)?xv[e].y:(kk==2)?xv[e].z:xv[e].w;
          f[e][0]+=x*wa.x; f[e][1]+=x*wa.y; f[e][2]+=x*wa.z; f[e][3]+=x*wa.w;
          f[e][4]+=x*wb.x; f[e][5]+=x*wb.y; f[e][6]+=x*wb.z; f[e][7]+=x*wb.w;
        }
      }
    }
    __syncthreads();   // srcs/dsts/dirs visible

    // ---- ts = x[src]*filt : split + pack to smem ----
    #pragma unroll
    for (int e=0;e<4;++e){
      int row = trow*4 + e;
      int s = srcs[row];
      const float* xp = &g_x[(size_t)s*H + tcol*8];
      float4 xa = *(const float4*)xp;
      float4 xb = *(const float4*)(xp+4);
      float v[8];
      v[0]=xa.x*f[e][0]; v[1]=xa.y*f[e][1]; v[2]=xa.z*f[e][2]; v[3]=xa.w*f[e][3];
      v[4]=xb.x*f[e][4]; v[5]=xb.y*f[e][5]; v[6]=xb.z*f[e][6]; v[7]=xb.w*f[e][7];
      unsigned hp[4], lp[4];
      #pragma unroll
      for (int j=0;j<4;++j){
        float h0,l0,h1,l1;
        bf16_split(v[2*j],   h0, l0);
        bf16_split(v[2*j+1], h1, l1);
        hp[j] = pack_bf16(h0, h1);
        lp[j] = pack_bf16(l0, l1);
      }
      *(uint4*)&tshiP[row*PADP + tcol*4] = make_uint4(hp[0],hp[1],hp[2],hp[3]);
      *(uint4*)&tsloP[row*PADP + tcol*4] = make_uint4(lp[0],lp[1],lp[2],lp[3]);
    }
    __syncthreads();   // ts complete

    // ---- phi GEMM: bf16x3, pure LDS + HMMA ----
    float d[2][4][4];
    #pragma unroll
    for (int ms=0;ms<2;++ms)
      #pragma unroll
      for (int ns=0;ns<4;++ns){ d[ms][ns][0]=0.f; d[ms][ns][1]=0.f; d[ms][ns][2]=0.f; d[ms][ns][3]=0.f; }

    #pragma unroll 2
    for (int ks = 0; ks < 8; ++ks){
      int kp = ks*8 + qc;
      unsigned ahi[2][4], alo[2][4];
      #pragma unroll
      for (int ms=0;ms<2;++ms){
        int r = wm*32 + ms*16 + qr;
        ahi[ms][0] = tshiP[r*PADP + kp];
        ahi[ms][1] = tshiP[(r+8)*PADP + kp];
        ahi[ms][2] = tshiP[r*PADP + kp + 4];
        ahi[ms][3] = tshiP[(r+8)*PADP + kp + 4];
        alo[ms][0] = tsloP[r*PADP + kp];
        alo[ms][1] = tsloP[(r+8)*PADP + kp];
        alo[ms][2] = tsloP[r*PADP + kp + 4];
        alo[ms][3] = tsloP[(r+8)*PADP + kp + 4];
      }
      unsigned bhi[4][2], blo[4][2];
      #pragma unroll
      for (int ns=0;ns<4;++ns){
        int n = wn*32 + ns*8 + qr;
        bhi[ns][0] = W1hiP[n*PADP + kp];
        bhi[ns][1] = W1hiP[n*PADP + kp + 4];
        blo[ns][0] = W1loP[n*PADP + kp];
        blo[ns][1] = W1loP[n*PADP + kp + 4];
      }
      #pragma unroll
      for (int ms=0;ms<2;++ms)
        #pragma unroll
        for (int ns=0;ns<4;++ns){
          mma16(d[ms][ns], ahi[ms], bhi[ns]);
          mma16(d[ms][ns], ahi[ms], blo[ns]);
          mma16(d[ms][ns], alo[ms], bhi[ns]);
        }
    }
    __syncthreads();   // all warps done reading ts/W1 packed for this tile

    // ---- store D fragments to smem (overlays ts region) ----
    #pragma unroll
    for (int ms=0;ms<2;++ms){
      int r = wm*32 + ms*16 + qr;
      #pragma unroll
      for (int ns=0;ns<4;++ns){
        int c = wn*32 + ns*8 + 2*qc;
        *(float2*)&Dm[r*PADT + c]     = make_float2(d[ms][ns][0], d[ms][ns][1]);
        *(float2*)&Dm[(r+8)*PADT + c] = make_float2(d[ms][ns][2], d[ms][ns][3]);
      }
    }
    __syncthreads();

    // ---- silu + scatter: thread owns edges trow*4..+3, cols tcol*8..+7 ----
    #pragma unroll
    for (int e=0;e<4;++e){
      int row = trow*4 + e;
      float4 va = *(const float4*)&Dm[row*PADT + tcol*8];
      float4 vb = *(const float4*)&Dm[row*PADT + tcol*8 + 4];
      float p[8];
      p[0]=silu_f(va.x); p[1]=silu_f(va.y); p[2]=silu_f(va.z); p[3]=silu_f(va.w);
      p[4]=silu_f(vb.x); p[5]=silu_f(vb.y); p[6]=silu_f(vb.z); p[7]=silu_f(vb.w);
      int s = srcs[row], dn = dsts[row];
      float dcs[3] = {dirs[row*3+0], dirs[row*3+1], dirs[row*3+2]};
      red4(&g_dx[(size_t)dn*H + tcol*8],     p[0], p[1], p[2], p[3]);
      red4(&g_dx[(size_t)dn*H + tcol*8 + 4], p[4], p[5], p[6], p[7]);
      if (hasv){
        #pragma unroll
        for (int c=0;c<3;++c){
          const float* vmp = &g_vmix[((size_t)s*3 + c)*H + tcol*8];
          float4 ma = *(const float4*)vmp;
          float4 mb = *(const float4*)(vmp+4);
          float* dvp = &g_dvec[((size_t)dn*3 + c)*H + tcol*8];
          red4(dvp,   ma.x*f[e][0] + p[0]*dcs[c], ma.y*f[e][1] + p[1]*dcs[c],
                      ma.z*f[e][2] + p[2]*dcs[c], ma.w*f[e][3] + p[3]*dcs[c]);
          red4(dvp+4, mb.x*f[e][4] + p[4]*dcs[c], mb.y*f[e][5] + p[5]*dcs[c],
                      mb.z*f[e][6] + p[6]*dcs[c], mb.w*f[e][7] + p[7]*dcs[c]);
        }
      } else {
        #pragma unroll
        for (int c=0;c<3;++c){
          float* dvp = &g_dvec[((size_t)dn*3 + c)*H + tcol*8];
          red4(dvp,   p[0]*dcs[c], p[1]*dcs[c], p[2]*dcs[c], p[3]*dcs[c]);
          red4(dvp+4, p[4]*dcs[c], p[5]*dcs[c], p[6]*dcs[c], p[7]*dcs[c]);
        }
      }
    }
  }
}

// ---------------- vnorm ----------------
__global__ void k_vnorm(){
  int idx = blockIdx.x*blockDim.x + threadIdx.x;
  if (idx >= NN*H) return;
  int n = idx >> 7, h = idx & 127;
  float a0 = g_vmix[((size_t)n*3+0)*H + h];
  float a1 = g_vmix[((size_t)n*3+1)*H + h];
  float a2 = g_vmix[((size_t)n*3+2)*H + h];
  g_dx[idx] = sqrtf(a0*a0 + a1*a1 + a2*a2 + 1e-8f);
}

// ---------------- a = silu([x, vnorm] @ Wa + ba) ----------------
#define PADA 264
__global__ __launch_bounds__(256, 1)
void k_mlp_a(const float* __restrict__ Wa, const float* __restrict__ ba){
  extern __shared__ float sm[];
  float* Was = sm;               // 256*128
  float* Xs  = Was + 256*H;      // 64*PADA
  float* bas = Xs + 64*PADA;     // 128
  int tid = threadIdx.x;
  int tcol = tid & 15, trow = tid >> 4;
  for (int i = tid; i < 256*H; i += 256) Was[i] = Wa[i];
  if (tid < H) bas[tid] = ba[tid];
  int ntiles = (NN + 63) >> 6;
  for (int t = blockIdx.x; t < ntiles; t += gridDim.x){
    __syncthreads();
    int r0 = t << 6;
    for (int i = tid; i < 64*256; i += 256){
      int rr = i >> 8, kk = i & 255;
      float v = 0.0f;
      if (r0 + rr < NN)
        v = (kk < H) ? g_x[(size_t)(r0+rr)*H + kk] : g_dx[(size_t)(r0+rr)*H + (kk-H)];
      Xs[rr*PADA + kk] = v;
    }
    __syncthreads();
    float acc[4][8];
    #pragma unroll
    for (int r=0;r<4;++r){
      #pragma unroll
      for (int c=0;c<8;++c) acc[r][c]=0.f;
    }
    #pragma unroll 2
    for (int k0 = 0; k0 < 256; k0 += 4){
      float4 xv[4];
      #pragma unroll
      for (int r=0;r<4;++r) xv[r] = *(const float4*)&Xs[(trow*4+r)*PADA + k0];
      #pragma unroll
      for (int kk=0;kk<4;++kk){
        float4 wa = *(const float4*)&Was[(k0+kk)*H + tcol*8];
        float4 wb = *(const float4*)&Was[(k0+kk)*H + tcol*8+4];
        #pragma unroll
        for (int r=0;r<4;++r){
          float x = (kk==0)?xv[r].x:(kk==1)?xv[r].y:(kk==2)?xv[r].z:xv[r].w;
          acc[r][0]+=x*wa.x; acc[r][1]+=x*wa.y; acc[r][2]+=x*wa.z; acc[r][3]+=x*wa.w;
          acc[r][4]+=x*wb.x; acc[r][5]+=x*wb.y; acc[r][6]+=x*wb.z; acc[r][7]+=x*wb.w;
        }
      }
    }
    #pragma unroll
    for (int r=0;r<4;++r){
      int row = r0 + trow*4 + r;
      if (row < NN){
        float* ap = &g_dvec[(size_t)row*H + tcol*8];
        #pragma unroll
        for (int c=0;c<8;++c) ap[c] = silu_f(acc[r][c] + bas[tcol*8+c]);
      }
    }
  }
}

// ---------------- out = a @ Wb + bb, pooled atomics ----------------
__global__ void k_poolout(const int* __restrict__ batch, const float* __restrict__ Wb,
                          const float* __restrict__ bb){
  extern __shared__ float sm[];
  float* Wbs = sm;
  float* bbs = Wbs + H*NOUT;
  float* as_ = bbs + NOUT;
  int tid = threadIdx.x;
  for (int i = tid; i < H*NOUT; i += 128) Wbs[i] = Wb[i];
  if (tid < NOUT) bbs[tid] = bb[tid];
  for (int n = blockIdx.x; n < NN; n += gridDim.x){
    __syncthreads();
    as_[tid] = g_dvec[(size_t)n*H + tid];
    __syncthreads();
    if (tid < NOUT){
      float o = bbs[tid];
      #pragma unroll 4
      for (int h = 0; h < H; ++h) o += as_[h] * Wbs[h*NOUT + tid];
      atomicAdd(&g_pooled[batch[n]*NOUT + tid], o);
    }
  }
}

// ---------------- output assembly ----------------
__global__ void k_out(float* __restrict__ out){
  int idx = blockIdx.x*blockDim.x + threadIdx.x;
  if (idx < NG*64){
    int g = idx >> 6, j = idx & 63;
    out[idx] = g_pooled[g*NOUT + j];
  } else if (idx < NG*64 + NG){
    int g = idx - NG*64;
    float v = g_pooled[g*NOUT + 64];
    out[idx] = fminf(fmaxf(v, -10.0f), 2.0f);
  }
}

// ---------------- launch ----------------
extern "C" void kernel_launch(void* const* d_in, const int* in_sizes, int n_in,
                              void* d_out, int out_size){
  const int*   z     = (const int*)  d_in[0];
  const float* pos   = (const float*)d_in[1];
  const int*   batch = (const int*)  d_in[2];
  const int*   ei    = (const int*)  d_in[3];
  const float* emb   = (const float*)d_in[4];
  const float* Wrbf  = (const float*)d_in[5];
  const float* W1    = (const float*)d_in[6];
  const float* Wo    = (const float*)d_in[7];
  const float* Wv    = (const float*)d_in[8];
  const float* Wvec2 = (const float*)d_in[10];
  const float* Wa    = (const float*)d_in[11];
  const float* ba    = (const float*)d_in[12];
  const float* Wb    = (const float*)d_in[13];
  const float* bb    = (const float*)d_in[14];
  float* out = (float*)d_out;

  float *p_x, *p_vec, *p_dx, *p_dvec, *p_vmix;
  cudaGetSymbolAddress((void**)&p_x,    g_x);
  cudaGetSymbolAddress((void**)&p_vec,  g_vec);
  cudaGetSymbolAddress((void**)&p_dx,   g_dx);
  cudaGetSymbolAddress((void**)&p_dvec, g_dvec);
  cudaGetSymbolAddress((void**)&p_vmix, g_vmix);

  const size_t gemm_smem = (size_t)(H*H + 64*PADX) * sizeof(float);
  const size_t edge_smem = (size_t)(NRBF*H) * sizeof(float)     // Wr
                         + (size_t)(4*H*PADP) * sizeof(unsigned) // W1hiP/W1loP/tshiP/tsloP
                         + (size_t)(ETILE*3) * sizeof(float)     // dirs
                         + 2*ETILE*sizeof(int);                  // srcs/dsts
  const size_t mlpa_smem = (size_t)(256*H + 64*PADA + H) * sizeof(float);
  const size_t pool_smem = (size_t)(H*NOUT + NOUT + H) * sizeof(float);

  cudaFuncSetAttribute(gemm_nk<false>, cudaFuncAttributeMaxDynamicSharedMemorySize, (int)gemm_smem);
  cudaFuncSetAttribute(gemm_nk<true>,  cudaFuncAttributeMaxDynamicSharedMemorySize, (int)gemm_smem);
  cudaFuncSetAttribute(gemm_add,       cudaFuncAttributeMaxDynamicSharedMemorySize, (int)gemm_smem);
  cudaFuncSetAttribute(k_edge,         cudaFuncAttributeMaxDynamicSharedMemorySize, (int)edge_smem);
  cudaFuncSetAttribute(k_mlp_a,        cudaFuncAttributeMaxDynamicSharedMemorySize, (int)mlpa_smem);
  cudaFuncSetAttribute(k_poolout,      cudaFuncAttributeMaxDynamicSharedMemorySize, (int)pool_smem);

  const int ZB = (NN*3*H + 255) / 256;

  k_init<<<ZB, 256>>>(z, emb);
  k_edgegeom<<<(NE + 255)/256, 256>>>(ei, pos);

  // ---- layer 0 (vec == 0: no vmix gemm; dx/dvec zeroed by k_init) ----
  k_edge<<<148, 512, edge_smem>>>(ei, Wrbf, W1, 0);
  gemm_nk<true><<<157, 128, gemm_smem>>>(p_dx, Wo, p_x, NN);

  // ---- layer 1: vec = vec + dvec0 (fused); vmix = vec @ Wv[1] ----
  gemm_add<<<296, 128, gemm_smem>>>(p_vec, p_dvec, Wv + (size_t)H*H, p_vmix, NN*3);
  k_zero<<<ZB, 256>>>();
  k_edge<<<148, 512, edge_smem>>>(ei, Wrbf + (size_t)NRBF*H, W1 + (size_t)H*H, 1);
  gemm_nk<true><<<157, 128, gemm_smem>>>(p_dx, Wo + (size_t)H*H, p_x, NN);

  // ---- readout: vec = vec + dvec1 (fused); v2 = vec @ Wvec2 ----
  gemm_add<<<296, 128, gemm_smem>>>(p_vec, p_dvec, Wvec2, p_vmix, NN*3);
  k_vnorm<<<(NN*H + 255)/256, 256>>>();
  k_mlp_a<<<157, 256, mlpa_smem>>>(Wa, ba);
  k_poolout<<<592, 128, pool_smem>>>(batch, Wb, bb);
  k_out<<<(NG*64 + NG + 255)/256, 256>>>(out);
}